// round 1
// baseline (speedup 1.0000x reference)
#include <cuda_runtime.h>
#include <math.h>

// ---------------- problem constants ----------------
#define B_   8
#define L_   512
#define D_   768
#define NL_  12
#define E_   8192
#define H_   12
#define DH_  64
#define DF_  3072
#define M_   4096       // B_*L_
#define TD_  2304       // 3*D_

// ---------------- scratch (static device memory; no allocations) ----------------
__device__ float g_h  [M_ * D_];
__device__ float g_qkv[M_ * TD_];
__device__ float g_P  [B_ * H_ * L_ * L_];   // attention probabilities (100 MB)
__device__ float g_ctx[M_ * D_];
__device__ float g_h1 [M_ * D_];
__device__ float g_res[M_ * D_];
__device__ float g_x  [M_ * D_];
__device__ float g_y  [M_ * D_];
__device__ float g_g  [M_ * D_];
__device__ float g_mid[M_ * DF_];
__device__ float g_adj[B_ * L_ * L_];        // dense normalized adjacency per batch
__device__ float g_dinv[B_ * L_];

// ---------------- helpers ----------------
__device__ __forceinline__ float gelu_f(float v) {
    return 0.5f * v * (1.0f + erff(v * 0.7071067811865475f));
}

// ---------------- generic tiled SGEMM with fused epilogues ----------------
// C[M,N] = epi( A[M,K] @ B[K,N] + bias , add )
// EPI: 0 = bias only, 1 = bias + add, 2 = gelu(bias+acc), 3 = add + gelu(bias+acc)
// batched over blockIdx.z with strides sA/sB/sC (add shares sC/ldc).
template <int EPI>
__global__ __launch_bounds__(256, 2)
void gemm_kernel(const float* __restrict__ A, const float* __restrict__ Bw,
                 const float* __restrict__ bias, const float* __restrict__ add,
                 float* __restrict__ C,
                 int K, int lda, int ldb, int ldc,
                 long sA, long sB, long sC)
{
    __shared__ float As[16][128];
    __shared__ float Bs[16][128];

    const long z = blockIdx.z;
    A  += z * sA;
    Bw += z * sB;
    C  += z * sC;
    const float* addp = add ? add + z * sC : (const float*)0;

    const int n0 = blockIdx.x * 128;
    const int m0 = blockIdx.y * 128;
    const int tid = threadIdx.x;
    const int tx = tid & 15;        // 0..15 (cols)
    const int ty = tid >> 4;        // 0..15 (rows)

    const int a_r = tid >> 2;         // 0..63
    const int a_c = (tid & 3) << 2;   // 0,4,8,12
    const int b_r = tid >> 5;         // 0..7
    const int b_c = (tid & 31) << 2;  // 0..124

    float acc[8][8];
    #pragma unroll
    for (int i = 0; i < 8; i++)
        #pragma unroll
        for (int j = 0; j < 8; j++) acc[i][j] = 0.f;

    const float* Ap0 = A + (long)(m0 + a_r) * lda + a_c;
    const float* Ap1 = A + (long)(m0 + a_r + 64) * lda + a_c;
    const float* Bp0 = Bw + (long)b_r * ldb + n0 + b_c;
    const float* Bp1 = Bw + (long)(b_r + 8) * ldb + n0 + b_c;

    for (int k0 = 0; k0 < K; k0 += 16) {
        float4 av0 = *(const float4*)(Ap0 + k0);
        float4 av1 = *(const float4*)(Ap1 + k0);
        float4 bv0 = *(const float4*)(Bp0 + (long)k0 * ldb);
        float4 bv1 = *(const float4*)(Bp1 + (long)k0 * ldb);
        __syncthreads();
        As[a_c + 0][a_r] = av0.x; As[a_c + 1][a_r] = av0.y;
        As[a_c + 2][a_r] = av0.z; As[a_c + 3][a_r] = av0.w;
        As[a_c + 0][a_r + 64] = av1.x; As[a_c + 1][a_r + 64] = av1.y;
        As[a_c + 2][a_r + 64] = av1.z; As[a_c + 3][a_r + 64] = av1.w;
        *(float4*)&Bs[b_r][b_c]     = bv0;
        *(float4*)&Bs[b_r + 8][b_c] = bv1;
        __syncthreads();
        #pragma unroll
        for (int kk = 0; kk < 16; kk++) {
            float a0[8], b0[8];
            *(float4*)&a0[0] = *(const float4*)&As[kk][ty * 4];
            *(float4*)&a0[4] = *(const float4*)&As[kk][64 + ty * 4];
            *(float4*)&b0[0] = *(const float4*)&Bs[kk][tx * 4];
            *(float4*)&b0[4] = *(const float4*)&Bs[kk][64 + tx * 4];
            #pragma unroll
            for (int i = 0; i < 8; i++)
                #pragma unroll
                for (int j = 0; j < 8; j++)
                    acc[i][j] += a0[i] * b0[j];
        }
    }

    float4 bias0 = make_float4(0.f, 0.f, 0.f, 0.f);
    float4 bias1 = bias0;
    if (bias) {
        bias0 = *(const float4*)&bias[n0 + tx * 4];
        bias1 = *(const float4*)&bias[n0 + 64 + tx * 4];
    }

    #pragma unroll
    for (int i = 0; i < 8; i++) {
        const int r = m0 + ((i < 4) ? (ty * 4 + i) : (60 + ty * 4 + i));
        #pragma unroll
        for (int half = 0; half < 2; half++) {
            const int col = n0 + half * 64 + tx * 4;
            const float4 bb = half ? bias1 : bias0;
            float4 v;
            v.x = acc[i][half * 4 + 0] + bb.x;
            v.y = acc[i][half * 4 + 1] + bb.y;
            v.z = acc[i][half * 4 + 2] + bb.z;
            v.w = acc[i][half * 4 + 3] + bb.w;
            if (EPI == 2 || EPI == 3) {
                v.x = gelu_f(v.x); v.y = gelu_f(v.y);
                v.z = gelu_f(v.z); v.w = gelu_f(v.w);
            }
            if (EPI == 1 || EPI == 3) {
                float4 ad = *(const float4*)&addp[(long)r * ldc + col];
                v.x += ad.x; v.y += ad.y; v.z += ad.z; v.w += ad.w;
            }
            *(float4*)&C[(long)r * ldc + col] = v;
        }
    }
}

// ---------------- LayerNorm (row = 768, block per row) ----------------
__global__ void ln_kernel(const float* __restrict__ in,
                          const float* __restrict__ gam,
                          const float* __restrict__ bet,
                          float* __restrict__ out)
{
    __shared__ float red[8];
    const int row = blockIdx.x;
    const int t = threadIdx.x;
    const int lane = t & 31, w = t >> 5;
    const float* xp = in + (long)row * D_;

    float v0 = xp[t], v1 = xp[t + 256], v2 = xp[t + 512];
    float s = v0 + v1 + v2;
    #pragma unroll
    for (int o = 16; o > 0; o >>= 1) s += __shfl_xor_sync(0xffffffffu, s, o);
    if (lane == 0) red[w] = s;
    __syncthreads();
    s = 0.f;
    #pragma unroll
    for (int i = 0; i < 8; i++) s += red[i];
    const float mean = s * (1.f / 768.f);
    __syncthreads();

    float d0 = v0 - mean, d1 = v1 - mean, d2 = v2 - mean;
    float q = d0 * d0 + d1 * d1 + d2 * d2;
    #pragma unroll
    for (int o = 16; o > 0; o >>= 1) q += __shfl_xor_sync(0xffffffffu, q, o);
    if (lane == 0) red[w] = q;
    __syncthreads();
    q = 0.f;
    #pragma unroll
    for (int i = 0; i < 8; i++) q += red[i];
    const float r = rsqrtf(q * (1.f / 768.f) + 1e-12f);

    float* op = out + (long)row * D_;
    op[t]       = d0 * r * gam[t]       + bet[t];
    op[t + 256] = d1 * r * gam[t + 256] + bet[t + 256];
    op[t + 512] = d2 * r * gam[t + 512] + bet[t + 512];
}

// ---------------- attention: scores + softmax -> P ----------------
// grid (B*H, L/64), 256 threads; K tile resident in smem [512][65]
__global__ void attn_scores_kernel(const float* __restrict__ qkv, float* __restrict__ P)
{
    extern __shared__ float sm[];
    float* Ks = sm;              // [512][65]
    float* qs = sm + 512 * 65;   // [64][65]
    const int bh = blockIdx.x;
    const int b = bh / H_, head = bh % H_;
    const int q0 = blockIdx.y * 64;
    const int tid = threadIdx.x;
    const float* base = qkv + (long)b * L_ * TD_;

    for (int id = tid; id < 512 * 16; id += 256) {
        int k = id >> 4, c = (id & 15) << 2;
        float4 v = *(const float4*)&base[(long)k * TD_ + D_ + head * DH_ + c];
        float* p = &Ks[k * 65 + c];
        p[0] = v.x; p[1] = v.y; p[2] = v.z; p[3] = v.w;
    }
    for (int id = tid; id < 64 * 16; id += 256) {
        int r = id >> 4, c = (id & 15) << 2;
        float4 v = *(const float4*)&base[(long)(q0 + r) * TD_ + head * DH_ + c];
        float* p = &qs[r * 65 + c];
        p[0] = v.x; p[1] = v.y; p[2] = v.z; p[3] = v.w;
    }
    __syncthreads();

    const int w = tid >> 5, lane = tid & 31;
    for (int rr = 0; rr < 8; rr++) {
        const int row = w * 8 + rr;
        float acc[16];
        #pragma unroll
        for (int j = 0; j < 16; j++) acc[j] = 0.f;
        const float* qp = &qs[row * 65];
        const float* kp = &Ks[lane * 65];
        #pragma unroll 4
        for (int d = 0; d < 64; d++) {
            float qd = qp[d];
            #pragma unroll
            for (int j = 0; j < 16; j++)
                acc[j] += qd * kp[j * (32 * 65) + d];
        }
        float mx = -3.0e38f;
        #pragma unroll
        for (int j = 0; j < 16; j++) { acc[j] *= 0.125f; mx = fmaxf(mx, acc[j]); }
        #pragma unroll
        for (int o = 16; o > 0; o >>= 1) mx = fmaxf(mx, __shfl_xor_sync(0xffffffffu, mx, o));
        float s = 0.f;
        #pragma unroll
        for (int j = 0; j < 16; j++) { acc[j] = __expf(acc[j] - mx); s += acc[j]; }
        #pragma unroll
        for (int o = 16; o > 0; o >>= 1) s += __shfl_xor_sync(0xffffffffu, s, o);
        const float inv = 1.f / s;
        float* Pp = P + ((long)bh * L_ + q0 + row) * L_;
        #pragma unroll
        for (int j = 0; j < 16; j++) Pp[lane + 32 * j] = acc[j] * inv;
    }
}

// ---------------- attention: ctx = P @ V ----------------
// grid (B*H, L/64), 256 threads; V resident in smem, P staged in 128-wide tiles
__global__ void attn_ctx_kernel(const float* __restrict__ qkv,
                                const float* __restrict__ P,
                                float* __restrict__ ctx)
{
    extern __shared__ float sm[];
    float* Vs = sm;              // [512][65]
    float* Ps = sm + 512 * 65;   // [64][132]
    const int bh = blockIdx.x;
    const int b = bh / H_, head = bh % H_;
    const int q0 = blockIdx.y * 64;
    const int tid = threadIdx.x;
    const float* base = qkv + (long)b * L_ * TD_;

    for (int id = tid; id < 512 * 16; id += 256) {
        int k = id >> 4, c = (id & 15) << 2;
        float4 v = *(const float4*)&base[(long)k * TD_ + 2 * D_ + head * DH_ + c];
        float* p = &Vs[k * 65 + c];
        p[0] = v.x; p[1] = v.y; p[2] = v.z; p[3] = v.w;
    }

    const int q = tid >> 2, dl = tid & 3;
    float acc[16];
    #pragma unroll
    for (int i = 0; i < 16; i++) acc[i] = 0.f;
    const float* Prow = P + ((long)bh * L_ + q0) * L_;

    for (int kt = 0; kt < 4; kt++) {
        __syncthreads();
        for (int id = tid; id < 64 * 32; id += 256) {
            int r = id >> 5, c = (id & 31) << 2;
            *(float4*)&Ps[r * 132 + c] =
                *(const float4*)&Prow[(long)r * L_ + kt * 128 + c];
        }
        __syncthreads();
        const float* pq = &Ps[q * 132];
        #pragma unroll 2
        for (int kk = 0; kk < 128; kk++) {
            float p = pq[kk];
            const float* vp = &Vs[(kt * 128 + kk) * 65 + dl];
            #pragma unroll
            for (int i = 0; i < 16; i++) acc[i] += p * vp[4 * i];
        }
    }
    float* cp = ctx + (long)(b * L_ + q0 + q) * D_ + head * DH_ + dl;
    #pragma unroll
    for (int i = 0; i < 16; i++) cp[4 * i] = acc[i];
}

// ---------------- GCN graph structure ----------------
__global__ void deg_kernel(const int* __restrict__ edges, float* __restrict__ dinv)
{
    __shared__ float sdeg[L_];
    const int b = blockIdx.x, t = threadIdx.x;
    sdeg[t] = 1.f;                      // self loop
    __syncthreads();
    const int* dst = edges + (long)b * 2 * E_ + E_;
    for (int e = t; e < E_; e += L_) atomicAdd(&sdeg[dst[e]], 1.f);
    __syncthreads();
    dinv[b * L_ + t] = rsqrtf(sdeg[t]);
}

__global__ void adj_edge_kernel(const int* __restrict__ edges,
                                const float* __restrict__ dinv,
                                float* __restrict__ adj)
{
    const int i = blockIdx.x * 256 + threadIdx.x;   // B*E
    const int b = i / E_, e = i % E_;
    const int s = edges[(long)b * 2 * E_ + e];
    const int d = edges[(long)b * 2 * E_ + E_ + e];
    atomicAdd(&adj[((long)b * L_ + d) * L_ + s], dinv[b * L_ + s] * dinv[b * L_ + d]);
}

__global__ void adj_diag_kernel(const float* __restrict__ dinv, float* __restrict__ adj)
{
    const int i = blockIdx.x * 256 + threadIdx.x;   // B*L
    const int b = i / L_, n = i % L_;
    const float di = dinv[i];
    adj[((long)b * L_ + n) * L_ + n] += di * di;
}

// ---------------- host side ----------------
static void launch_gemm(int epi, const float* A, const float* Bw, const float* bias,
                        const float* add, float* C, int Mr, int Nr, int K,
                        int lda, int ldb, int ldc, int batch,
                        long sA, long sB, long sC)
{
    dim3 grid(Nr / 128, Mr / 128, batch), block(256);
    switch (epi) {
        case 0: gemm_kernel<0><<<grid, block>>>(A, Bw, bias, add, C, K, lda, ldb, ldc, sA, sB, sC); break;
        case 1: gemm_kernel<1><<<grid, block>>>(A, Bw, bias, add, C, K, lda, ldb, ldc, sA, sB, sC); break;
        case 2: gemm_kernel<2><<<grid, block>>>(A, Bw, bias, add, C, K, lda, ldb, ldc, sA, sB, sC); break;
        case 3: gemm_kernel<3><<<grid, block>>>(A, Bw, bias, add, C, K, lda, ldb, ldc, sA, sB, sC); break;
    }
}

extern "C" void kernel_launch(void* const* d_in, const int* in_sizes, int n_in,
                              void* d_out, int out_size)
{
    const float* hidden = (const float*)d_in[0];
    const int*   edges  = (const int*)  d_in[1];
    const float* Wqkv   = (const float*)d_in[2];
    const float* bqkv   = (const float*)d_in[3];
    const float* Wo     = (const float*)d_in[4];
    const float* bo     = (const float*)d_in[5];
    const float* ln1_s  = (const float*)d_in[6];
    const float* ln1_b  = (const float*)d_in[7];
    const float* n1_s   = (const float*)d_in[8];
    const float* n1_b   = (const float*)d_in[9];
    const float* m1_W   = (const float*)d_in[10];
    const float* m1_b   = (const float*)d_in[11];
    const float* c1_W   = (const float*)d_in[12];
    const float* c1_b   = (const float*)d_in[13];
    const float* c2_W   = (const float*)d_in[14];
    const float* c2_b   = (const float*)d_in[15];
    const float* n2_s   = (const float*)d_in[16];
    const float* n2_b   = (const float*)d_in[17];
    const float* m2_W   = (const float*)d_in[18];
    const float* m2_b   = (const float*)d_in[19];
    const float* m3_W   = (const float*)d_in[20];
    const float* m3_b   = (const float*)d_in[21];
    const float* int_W  = (const float*)d_in[22];
    const float* int_b  = (const float*)d_in[23];
    const float* out_W  = (const float*)d_in[24];
    const float* out_b  = (const float*)d_in[25];
    const float* ln2_s  = (const float*)d_in[26];
    const float* ln2_b  = (const float*)d_in[27];

    float *h, *qkv, *P, *ctx, *h1, *res, *x, *y, *gg, *mid, *adj, *dinv;
    cudaGetSymbolAddress((void**)&h,    g_h);
    cudaGetSymbolAddress((void**)&qkv,  g_qkv);
    cudaGetSymbolAddress((void**)&P,    g_P);
    cudaGetSymbolAddress((void**)&ctx,  g_ctx);
    cudaGetSymbolAddress((void**)&h1,   g_h1);
    cudaGetSymbolAddress((void**)&res,  g_res);
    cudaGetSymbolAddress((void**)&x,    g_x);
    cudaGetSymbolAddress((void**)&y,    g_y);
    cudaGetSymbolAddress((void**)&gg,   g_g);
    cudaGetSymbolAddress((void**)&mid,  g_mid);
    cudaGetSymbolAddress((void**)&adj,  g_adj);
    cudaGetSymbolAddress((void**)&dinv, g_dinv);

    const int SMEM_SCORES = (512 * 65 + 64 * 65) * 4;   // 149760
    const int SMEM_CTX    = (512 * 65 + 64 * 132) * 4;  // 166912
    cudaFuncSetAttribute(attn_scores_kernel, cudaFuncAttributeMaxDynamicSharedMemorySize, SMEM_SCORES);
    cudaFuncSetAttribute(attn_ctx_kernel,    cudaFuncAttributeMaxDynamicSharedMemorySize, SMEM_CTX);

    // setup: hidden copy + graph structure (same for all layers)
    cudaMemcpyAsync(h, hidden, sizeof(float) * M_ * D_, cudaMemcpyDeviceToDevice);
    deg_kernel<<<B_, L_>>>(edges, dinv);
    cudaMemsetAsync(adj, 0, sizeof(float) * B_ * L_ * L_);
    adj_edge_kernel<<<(B_ * E_) / 256, 256>>>(edges, dinv, adj);
    adj_diag_kernel<<<(B_ * L_) / 256, 256>>>(dinv, adj);

    const long sAdj = (long)L_ * L_;
    const long sBat = (long)L_ * D_;

    for (int l = 0; l < NL_; l++) {
        const float* Wqkv_l = Wqkv + (long)l * D_ * TD_;
        const float* bqkv_l = bqkv + (long)l * TD_;
        const float* Wo_l   = Wo   + (long)l * D_ * D_;
        const float* bo_l   = bo   + (long)l * D_;
        const float* ln1s   = ln1_s + (long)l * D_;
        const float* ln1b   = ln1_b + (long)l * D_;
        const float* n1s    = n1_s + (long)l * D_;
        const float* n1b    = n1_b + (long)l * D_;
        const float* m1W    = m1_W + (long)l * D_ * D_;
        const float* m1b    = m1_b + (long)l * D_;
        const float* c1W    = c1_W + (long)l * D_ * D_;
        const float* c1b    = c1_b + (long)l * D_;
        const float* c2W    = c2_W + (long)l * D_ * D_;
        const float* c2b    = c2_b + (long)l * D_;
        const float* n2s    = n2_s + (long)l * D_;
        const float* n2b    = n2_b + (long)l * D_;
        const float* m2W    = m2_W + (long)l * D_ * D_;
        const float* m2b    = m2_b + (long)l * D_;
        const float* m3W    = m3_W + (long)l * D_ * D_;
        const float* m3b    = m3_b + (long)l * D_;
        const float* intW   = int_W + (long)l * D_ * DF_;
        const float* intb   = int_b + (long)l * DF_;
        const float* outW   = out_W + (long)l * DF_ * D_;
        const float* outb   = out_b + (long)l * D_;
        const float* ln2s   = ln2_s + (long)l * D_;
        const float* ln2b   = ln2_b + (long)l * D_;

        // qkv = h @ Wqkv + b
        launch_gemm(0, h, Wqkv_l, bqkv_l, 0, qkv, M_, TD_, D_, D_, TD_, TD_, 1, 0, 0, 0);
        // attention
        attn_scores_kernel<<<dim3(B_ * H_, L_ / 64), 256, SMEM_SCORES>>>(qkv, P);
        attn_ctx_kernel<<<dim3(B_ * H_, L_ / 64), 256, SMEM_CTX>>>(qkv, P, ctx);
        // pre1 = ctx @ Wo + bo + h  -> y ; h1 = LN(pre1)
        launch_gemm(1, ctx, Wo_l, bo_l, h, y, M_, D_, D_, D_, D_, D_, 1, 0, 0, 0);
        ln_kernel<<<M_, 256>>>(y, ln1s, ln1b, h1);
        // res = gelu(h1 @ m3 + b)
        launch_gemm(2, h1, m3W, m3b, 0, res, M_, D_, D_, D_, D_, D_, 1, 0, 0, 0);
        // x = gelu(LN(h1,n1) @ m1 + b)
        ln_kernel<<<M_, 256>>>(h1, n1s, n1b, y);
        launch_gemm(2, y, m1W, m1b, 0, x, M_, D_, D_, D_, D_, D_, 1, 0, 0, 0);
        // GCN 1: xw = x @ c1W ; x = gelu(Adj @ xw + c1b)
        launch_gemm(0, x, c1W, 0, 0, y, M_, D_, D_, D_, D_, D_, 1, 0, 0, 0);
        launch_gemm(2, adj, y, c1b, 0, x, L_, D_, L_, L_, D_, D_, B_, sAdj, sBat, sBat);
        // GCN 2
        launch_gemm(0, x, c2W, 0, 0, y, M_, D_, D_, D_, D_, D_, 1, 0, 0, 0);
        launch_gemm(2, adj, y, c2b, 0, x, L_, D_, L_, L_, D_, D_, B_, sAdj, sBat, sBat);
        // g = res + gelu(LN(x,n2) @ m2 + b)
        ln_kernel<<<M_, 256>>>(x, n2s, n2b, y);
        launch_gemm(3, y, m2W, m2b, res, gg, M_, D_, D_, D_, D_, D_, 1, 0, 0, 0);
        // FFN: mid = gelu(g @ intW + b); pre2 = mid @ outW + b + g; h = LN(pre2)
        launch_gemm(2, gg, intW, intb, 0, mid, M_, DF_, D_, D_, DF_, DF_, 1, 0, 0, 0);
        launch_gemm(1, mid, outW, outb, gg, y, M_, D_, DF_, DF_, D_, D_, 1, 0, 0, 0);
        ln_kernel<<<M_, 256>>>(y, ln2s, ln2b, (l == NL_ - 1) ? (float*)d_out : h);
    }
}

// round 5
// speedup vs baseline: 1.2289x; 1.2289x over previous
#include <cuda_runtime.h>
#include <math.h>
#include <stdint.h>

// ---------------- problem constants ----------------
#define B_   8
#define L_   512
#define D_   768
#define NL_  12
#define E_   8192
#define H_   12
#define DH_  64
#define DF_  3072
#define M_   4096       // B_*L_
#define TD_  2304       // 3*D_

// ---------------- mma-gemm tile config ----------------
#define TM_T 128
#define TN_T 256
#define TK_T 32
#define AST  36                      // padded row stride (floats)
#define A_FLOATS (TM_T * AST)        // 4608
#define B_FLOATS (TN_T * AST)        // 9216
#define SMEM_MMA ((2 * A_FLOATS + 4 * B_FLOATS) * 4)   // 184320 bytes

// ---------------- scratch (static device memory) ----------------
__device__ float g_h  [M_ * D_];
__device__ float g_qkv[M_ * TD_];
__device__ float g_P  [B_ * H_ * L_ * L_];
__device__ float g_ctx[M_ * D_];
__device__ float g_h1 [M_ * D_];
__device__ float g_res[M_ * D_];
__device__ float g_x  [M_ * D_];
__device__ float g_y  [M_ * D_];
__device__ float g_g  [M_ * D_];
__device__ float g_mid[M_ * DF_];
__device__ float g_adj[B_ * L_ * L_];
__device__ float g_dinv[B_ * L_];
__device__ float g_yth[B_ * D_ * L_];        // transposed activations hi
__device__ float g_ytl[B_ * D_ * L_];        // transposed activations lo
__device__ float g_wTh[120324096];           // transposed weights hi (tf32)
__device__ float g_wTl[120324096];           // transposed weights lo (tf32)

// transposed-weight offsets (floats)
#define OFF_QKV 0L
#define OFF_WO  21233664L
#define OFF_M1  28311552L
#define OFF_C1  35389440L
#define OFF_C2  42467328L
#define OFF_M2  49545216L
#define OFF_M3  56623104L
#define OFF_INT 63700992L
#define OFF_OUT 92012544L

// ---------------- helpers ----------------
__device__ __forceinline__ uint32_t smem_u32(const void* p) {
    uint32_t a;
    asm("{ .reg .u64 t; cvta.to.shared.u64 t, %1; cvt.u32.u64 %0, t; }" : "=r"(a) : "l"(p));
    return a;
}
__device__ __forceinline__ float gelu_f(float v) {
    return 0.5f * v * (1.0f + erff(v * 0.7071067811865475f));
}
__device__ __forceinline__ float to_tf32(float x) {
    float r; asm("cvt.rna.tf32.f32 %0, %1;" : "=f"(r) : "f"(x)); return r;
}
__device__ __forceinline__ uint32_t tf32_bits(float x) {
    uint32_t r; asm("cvt.rna.tf32.f32 %0, %1;" : "=r"(r) : "f"(x)); return r;
}
__device__ __forceinline__ void cp16(uint32_t dst, const void* src) {
    asm volatile("cp.async.cg.shared.global [%0], [%1], 16;" :: "r"(dst), "l"(src));
}
#define CP_COMMIT() asm volatile("cp.async.commit_group;" ::: "memory")
#define CP_WAIT(n)  asm volatile("cp.async.wait_group %0;" :: "n"(n) : "memory")

__device__ __forceinline__ void mma_tf32(float c[4], const uint32_t a[4],
                                         uint32_t b0, uint32_t b1) {
    asm volatile(
        "mma.sync.aligned.m16n8k8.row.col.f32.tf32.tf32.f32 "
        "{%0,%1,%2,%3}, {%4,%5,%6,%7}, {%8,%9}, {%0,%1,%2,%3};"
        : "+f"(c[0]), "+f"(c[1]), "+f"(c[2]), "+f"(c[3])
        : "r"(a[0]), "r"(a[1]), "r"(a[2]), "r"(a[3]), "r"(b0), "r"(b1));
}

// ---------------- 3xTF32 mma.sync GEMM ----------------
// C[M,N] = epi( A[M,K] @ (Bh+Bl)[N,K]^T + bias , add )
// EPI: 0=bias, 1=bias+add, 2=gelu(bias+acc), 3=gelu(bias+acc)+add
template <int EPI>
__global__ __launch_bounds__(256, 1)
void mma_gemm(const float* __restrict__ A,
              const float* __restrict__ Bh, const float* __restrict__ Bl,
              const float* __restrict__ bias, const float* __restrict__ add,
              float* __restrict__ C, int K, int N, long sA, long sB, long sC)
{
    extern __shared__ float sm[];
    float* Asm  = sm;                                   // [2][128][36]
    float* Bhsm = sm + 2 * A_FLOATS;                    // [2][256][36]
    float* Blsm = sm + 2 * A_FLOATS + 2 * B_FLOATS;     // [2][256][36]
    const uint32_t sA_u  = smem_u32(Asm);
    const uint32_t sBh_u = smem_u32(Bhsm);
    const uint32_t sBl_u = smem_u32(Blsm);

    const int tid = threadIdx.x;
    const long z = blockIdx.z;
    A  += z * sA;
    Bh += z * sB;
    Bl += z * sB;
    C  += z * sC;
    const float* addp = (EPI == 1 || EPI == 3) ? add + z * sC : (const float*)0;

    const int m0 = blockIdx.y * TM_T;
    const int n0 = blockIdx.x * TN_T;
    const int wid = tid >> 5, lane = tid & 31;
    const int wm = wid >> 2, wn = wid & 3;       // 2 x 4 warps
    const int gid = lane >> 2, tq = lane & 3;

    float c[4][8][4];
    #pragma unroll
    for (int mt = 0; mt < 4; mt++)
        #pragma unroll
        for (int nt = 0; nt < 8; nt++)
            #pragma unroll
            for (int i = 0; i < 4; i++) c[mt][nt][i] = 0.f;

    const int nck = K / TK_T;

    auto prefetch = [&](int s, int k0) {
        #pragma unroll
        for (int i = 0; i < 4; i++) {
            int t = tid + i * 256;
            int r = t >> 3, cc = t & 7;
            cp16(sA_u + (s * A_FLOATS + r * AST + cc * 4) * 4,
                 A + (long)(m0 + r) * K + k0 + cc * 4);
        }
        #pragma unroll
        for (int i = 0; i < 8; i++) {
            int t = tid + i * 256;
            int r = t >> 3, cc = t & 7;
            cp16(sBh_u + (s * B_FLOATS + r * AST + cc * 4) * 4,
                 Bh + (long)(n0 + r) * K + k0 + cc * 4);
        }
        #pragma unroll
        for (int i = 0; i < 8; i++) {
            int t = tid + i * 256;
            int r = t >> 3, cc = t & 7;
            cp16(sBl_u + (s * B_FLOATS + r * AST + cc * 4) * 4,
                 Bl + (long)(n0 + r) * K + k0 + cc * 4);
        }
        CP_COMMIT();
    };

    prefetch(0, 0);

    for (int ck = 0; ck < nck; ck++) {
        if (ck + 1 < nck) {
            prefetch((ck + 1) & 1, (ck + 1) * TK_T);
            CP_WAIT(1);
        } else {
            CP_WAIT(0);
        }
        __syncthreads();

        const float* Ab  = Asm  + (ck & 1) * A_FLOATS + (wm * 64) * AST;
        const float* Bhb = Bhsm + (ck & 1) * B_FLOATS + (wn * 64) * AST;
        const float* Blb = Blsm + (ck & 1) * B_FLOATS + (wn * 64) * AST;

        #pragma unroll
        for (int k8 = 0; k8 < 4; k8++) {
            const int kc = k8 * 8 + tq;
            uint32_t ah[4][4], al[4][4];
            #pragma unroll
            for (int mt = 0; mt < 4; mt++) {
                #pragma unroll
                for (int q = 0; q < 4; q++) {
                    const int rr = mt * 16 + gid + (q & 1) * 8;
                    const int kk = kc + (q >> 1) * 4;
                    float a = Ab[rr * AST + kk];
                    uint32_t hi = tf32_bits(a);
                    ah[mt][q] = hi;
                    al[mt][q] = tf32_bits(a - __uint_as_float(hi));
                }
            }
            uint32_t bh[8][2], bl[8][2];
            #pragma unroll
            for (int nt = 0; nt < 8; nt++) {
                const int rr = (nt * 8 + gid) * AST + kc;
                bh[nt][0] = __float_as_uint(Bhb[rr]);
                bh[nt][1] = __float_as_uint(Bhb[rr + 4]);
                bl[nt][0] = __float_as_uint(Blb[rr]);
                bl[nt][1] = __float_as_uint(Blb[rr + 4]);
            }
            #pragma unroll
            for (int mt = 0; mt < 4; mt++)
                #pragma unroll
                for (int nt = 0; nt < 8; nt++) {
                    mma_tf32(c[mt][nt], al[mt], bh[nt][0], bh[nt][1]);
                    mma_tf32(c[mt][nt], ah[mt], bl[nt][0], bl[nt][1]);
                    mma_tf32(c[mt][nt], ah[mt], bh[nt][0], bh[nt][1]);
                }
        }
        __syncthreads();
    }

    // ---- epilogue ----
    #pragma unroll
    for (int mt = 0; mt < 4; mt++) {
        const int r0 = m0 + wm * 64 + mt * 16 + gid;
        #pragma unroll
        for (int nt = 0; nt < 8; nt++) {
            const int col = n0 + wn * 64 + nt * 8 + tq * 2;
            float bx = 0.f, by = 0.f;
            if (bias) { bx = bias[col]; by = bias[col + 1]; }
            #pragma unroll
            for (int half = 0; half < 2; half++) {
                const int r = r0 + half * 8;
                float vx = c[mt][nt][half * 2 + 0] + bx;
                float vy = c[mt][nt][half * 2 + 1] + by;
                if (EPI == 2 || EPI == 3) { vx = gelu_f(vx); vy = gelu_f(vy); }
                if (EPI == 1 || EPI == 3) {
                    const float* ap = &addp[(long)r * N + col];
                    vx += ap[0]; vy += ap[1];
                }
                float2 v = make_float2(vx, vy);
                *(float2*)&C[(long)r * N + col] = v;
            }
        }
    }
}

// ---------------- split transpose: in[Z][R][C] -> hi/lo out[Z][C][R] ----------------
__global__ void transpose_split(const float* __restrict__ in,
                                float* __restrict__ outh, float* __restrict__ outl,
                                int R, int C)
{
    __shared__ float t[32][33];
    const long z = blockIdx.z;
    in   += z * (long)R * C;
    outh += z * (long)R * C;
    outl += z * (long)R * C;
    const int c0 = blockIdx.x * 32, r0 = blockIdx.y * 32;
    const int tx = threadIdx.x, ty = threadIdx.y;
    #pragma unroll
    for (int i = 0; i < 32; i += 8)
        t[ty + i][tx] = in[(long)(r0 + ty + i) * C + c0 + tx];
    __syncthreads();
    #pragma unroll
    for (int i = 0; i < 32; i += 8) {
        float v = t[tx][ty + i];
        float hi = to_tf32(v);
        float lo = to_tf32(v - hi);
        outh[(long)(c0 + ty + i) * R + r0 + tx] = hi;
        outl[(long)(c0 + ty + i) * R + r0 + tx] = lo;
    }
}

// ---------------- LayerNorm ----------------
__global__ void ln_kernel(const float* __restrict__ in,
                          const float* __restrict__ gam,
                          const float* __restrict__ bet,
                          float* __restrict__ out)
{
    __shared__ float red[8];
    const int row = blockIdx.x;
    const int t = threadIdx.x;
    const int lane = t & 31, w = t >> 5;
    const float* xp = in + (long)row * D_;

    float v0 = xp[t], v1 = xp[t + 256], v2 = xp[t + 512];
    float s = v0 + v1 + v2;
    #pragma unroll
    for (int o = 16; o > 0; o >>= 1) s += __shfl_xor_sync(0xffffffffu, s, o);
    if (lane == 0) red[w] = s;
    __syncthreads();
    s = 0.f;
    #pragma unroll
    for (int i = 0; i < 8; i++) s += red[i];
    const float mean = s * (1.f / 768.f);
    __syncthreads();

    float d0 = v0 - mean, d1 = v1 - mean, d2 = v2 - mean;
    float q = d0 * d0 + d1 * d1 + d2 * d2;
    #pragma unroll
    for (int o = 16; o > 0; o >>= 1) q += __shfl_xor_sync(0xffffffffu, q, o);
    if (lane == 0) red[w] = q;
    __syncthreads();
    q = 0.f;
    #pragma unroll
    for (int i = 0; i < 8; i++) q += red[i];
    const float r = rsqrtf(q * (1.f / 768.f) + 1e-12f);

    float* op = out + (long)row * D_;
    op[t]       = d0 * r * gam[t]       + bet[t];
    op[t + 256] = d1 * r * gam[t + 256] + bet[t + 256];
    op[t + 512] = d2 * r * gam[t + 512] + bet[t + 512];
}

// ---------------- attention: scores + softmax -> P ----------------
__global__ void attn_scores_kernel(const float* __restrict__ qkv, float* __restrict__ P)
{
    extern __shared__ float smf[];
    float* Ks = smf;
    float* qs = smf + 512 * 65;
    const int bh = blockIdx.x;
    const int b = bh / H_, head = bh % H_;
    const int q0 = blockIdx.y * 64;
    const int tid = threadIdx.x;
    const float* base = qkv + (long)b * L_ * TD_;

    for (int id = tid; id < 512 * 16; id += 256) {
        int k = id >> 4, c = (id & 15) << 2;
        float4 v = *(const float4*)&base[(long)k * TD_ + D_ + head * DH_ + c];
        float* p = &Ks[k * 65 + c];
        p[0] = v.x; p[1] = v.y; p[2] = v.z; p[3] = v.w;
    }
    for (int id = tid; id < 64 * 16; id += 256) {
        int r = id >> 4, c = (id & 15) << 2;
        float4 v = *(const float4*)&base[(long)(q0 + r) * TD_ + head * DH_ + c];
        float* p = &qs[r * 65 + c];
        p[0] = v.x; p[1] = v.y; p[2] = v.z; p[3] = v.w;
    }
    __syncthreads();

    const int w = tid >> 5, lane = tid & 31;
    for (int rr = 0; rr < 8; rr++) {
        const int row = w * 8 + rr;
        float acc[16];
        #pragma unroll
        for (int j = 0; j < 16; j++) acc[j] = 0.f;
        const float* qp = &qs[row * 65];
        const float* kp = &Ks[lane * 65];
        #pragma unroll 4
        for (int d = 0; d < 64; d++) {
            float qd = qp[d];
            #pragma unroll
            for (int j = 0; j < 16; j++)
                acc[j] += qd * kp[j * (32 * 65) + d];
        }
        float mx = -3.0e38f;
        #pragma unroll
        for (int j = 0; j < 16; j++) { acc[j] *= 0.125f; mx = fmaxf(mx, acc[j]); }
        #pragma unroll
        for (int o = 16; o > 0; o >>= 1) mx = fmaxf(mx, __shfl_xor_sync(0xffffffffu, mx, o));
        float s = 0.f;
        #pragma unroll
        for (int j = 0; j < 16; j++) { acc[j] = __expf(acc[j] - mx); s += acc[j]; }
        #pragma unroll
        for (int o = 16; o > 0; o >>= 1) s += __shfl_xor_sync(0xffffffffu, s, o);
        const float inv = 1.f / s;
        float* Pp = P + ((long)bh * L_ + q0 + row) * L_;
        #pragma unroll
        for (int j = 0; j < 16; j++) Pp[lane + 32 * j] = acc[j] * inv;
    }
}

// ---------------- attention: ctx = P @ V ----------------
__global__ void attn_ctx_kernel(const float* __restrict__ qkv,
                                const float* __restrict__ P,
                                float* __restrict__ ctx)
{
    extern __shared__ float smf[];
    float* Vs = smf;
    float* Ps = smf + 512 * 65;
    const int bh = blockIdx.x;
    const int b = bh / H_, head = bh % H_;
    const int q0 = blockIdx.y * 64;
    const int tid = threadIdx.x;
    const float* base = qkv + (long)b * L_ * TD_;

    for (int id = tid; id < 512 * 16; id += 256) {
        int k = id >> 4, c = (id & 15) << 2;
        float4 v = *(const float4*)&base[(long)k * TD_ + 2 * D_ + head * DH_ + c];
        float* p = &Vs[k * 65 + c];
        p[0] = v.x; p[1] = v.y; p[2] = v.z; p[3] = v.w;
    }

    const int q = tid >> 2, dl = tid & 3;
    float acc[16];
    #pragma unroll
    for (int i = 0; i < 16; i++) acc[i] = 0.f;
    const float* Prow = P + ((long)bh * L_ + q0) * L_;

    for (int kt = 0; kt < 4; kt++) {
        __syncthreads();
        for (int id = tid; id < 64 * 32; id += 256) {
            int r = id >> 5, c = (id & 31) << 2;
            *(float4*)&Ps[r * 132 + c] =
                *(const float4*)&Prow[(long)r * L_ + kt * 128 + c];
        }
        __syncthreads();
        const float* pq = &Ps[q * 132];
        #pragma unroll 2
        for (int kk = 0; kk < 128; kk++) {
            float p = pq[kk];
            const float* vp = &Vs[(kt * 128 + kk) * 65 + dl];
            #pragma unroll
            for (int i = 0; i < 16; i++) acc[i] += p * vp[4 * i];
        }
    }
    float* cp = ctx + (long)(b * L_ + q0 + q) * D_ + head * DH_ + dl;
    #pragma unroll
    for (int i = 0; i < 16; i++) cp[4 * i] = acc[i];
}

// ---------------- GCN graph structure ----------------
__global__ void deg_kernel(const int* __restrict__ edges, float* __restrict__ dinv)
{
    __shared__ float sdeg[L_];
    const int b = blockIdx.x, t = threadIdx.x;
    sdeg[t] = 1.f;
    __syncthreads();
    const int* dst = edges + (long)b * 2 * E_ + E_;
    for (int e = t; e < E_; e += L_) atomicAdd(&sdeg[dst[e]], 1.f);
    __syncthreads();
    dinv[b * L_ + t] = rsqrtf(sdeg[t]);
}

__global__ void adj_edge_kernel(const int* __restrict__ edges,
                                const float* __restrict__ dinv,
                                float* __restrict__ adj)
{
    const int i = blockIdx.x * 256 + threadIdx.x;
    const int b = i / E_, e = i % E_;
    const int s = edges[(long)b * 2 * E_ + e];
    const int d = edges[(long)b * 2 * E_ + E_ + e];
    atomicAdd(&adj[((long)b * L_ + d) * L_ + s], dinv[b * L_ + s] * dinv[b * L_ + d]);
}

__global__ void adj_diag_kernel(const float* __restrict__ dinv, float* __restrict__ adj)
{
    const int i = blockIdx.x * 256 + threadIdx.x;
    const int b = i / L_, n = i % L_;
    const float di = dinv[i];
    adj[((long)b * L_ + n) * L_ + n] += di * di;
}

// ---------------- host side ----------------
static void launch_mma(int epi, const float* A, const float* Bh, const float* Bl,
                       const float* bias, const float* add, float* C,
                       int Mr, int N, int K, int batch,
                       long sA, long sB, long sC)
{
    dim3 grid(N / TN_T, Mr / TM_T, batch), block(256);
    switch (epi) {
        case 0: mma_gemm<0><<<grid, block, SMEM_MMA>>>(A, Bh, Bl, bias, add, C, K, N, sA, sB, sC); break;
        case 1: mma_gemm<1><<<grid, block, SMEM_MMA>>>(A, Bh, Bl, bias, add, C, K, N, sA, sB, sC); break;
        case 2: mma_gemm<2><<<grid, block, SMEM_MMA>>>(A, Bh, Bl, bias, add, C, K, N, sA, sB, sC); break;
        case 3: mma_gemm<3><<<grid, block, SMEM_MMA>>>(A, Bh, Bl, bias, add, C, K, N, sA, sB, sC); break;
    }
}

extern "C" void kernel_launch(void* const* d_in, const int* in_sizes, int n_in,
                              void* d_out, int out_size)
{
    const float* hidden = (const float*)d_in[0];
    const int*   edges  = (const int*)  d_in[1];
    const float* Wqkv   = (const float*)d_in[2];
    const float* bqkv   = (const float*)d_in[3];
    const float* Wo     = (const float*)d_in[4];
    const float* bo     = (const float*)d_in[5];
    const float* ln1_s  = (const float*)d_in[6];
    const float* ln1_b  = (const float*)d_in[7];
    const float* n1_s   = (const float*)d_in[8];
    const float* n1_b   = (const float*)d_in[9];
    const float* m1_W   = (const float*)d_in[10];
    const float* m1_b   = (const float*)d_in[11];
    const float* c1_W   = (const float*)d_in[12];
    const float* c1_b   = (const float*)d_in[13];
    const float* c2_W   = (const float*)d_in[14];
    const float* c2_b   = (const float*)d_in[15];
    const float* n2_s   = (const float*)d_in[16];
    const float* n2_b   = (const float*)d_in[17];
    const float* m2_W   = (const float*)d_in[18];
    const float* m2_b   = (const float*)d_in[19];
    const float* m3_W   = (const float*)d_in[20];
    const float* m3_b   = (const float*)d_in[21];
    const float* int_W  = (const float*)d_in[22];
    const float* int_b  = (const float*)d_in[23];
    const float* out_W  = (const float*)d_in[24];
    const float* out_b  = (const float*)d_in[25];
    const float* ln2_s  = (const float*)d_in[26];
    const float* ln2_b  = (const float*)d_in[27];

    float *h, *qkv, *P, *ctx, *h1, *res, *x, *y, *gg, *mid, *adj, *dinv, *yth, *ytl, *wTh, *wTl;
    cudaGetSymbolAddress((void**)&h,    g_h);
    cudaGetSymbolAddress((void**)&qkv,  g_qkv);
    cudaGetSymbolAddress((void**)&P,    g_P);
    cudaGetSymbolAddress((void**)&ctx,  g_ctx);
    cudaGetSymbolAddress((void**)&h1,   g_h1);
    cudaGetSymbolAddress((void**)&res,  g_res);
    cudaGetSymbolAddress((void**)&x,    g_x);
    cudaGetSymbolAddress((void**)&y,    g_y);
    cudaGetSymbolAddress((void**)&gg,   g_g);
    cudaGetSymbolAddress((void**)&mid,  g_mid);
    cudaGetSymbolAddress((void**)&adj,  g_adj);
    cudaGetSymbolAddress((void**)&dinv, g_dinv);
    cudaGetSymbolAddress((void**)&yth,  g_yth);
    cudaGetSymbolAddress((void**)&ytl,  g_ytl);
    cudaGetSymbolAddress((void**)&wTh,  g_wTh);
    cudaGetSymbolAddress((void**)&wTl,  g_wTl);

    const int SMEM_SCORES = (512 * 65 + 64 * 65) * 4;
    const int SMEM_CTX    = (512 * 65 + 64 * 132) * 4;
    cudaFuncSetAttribute(attn_scores_kernel, cudaFuncAttributeMaxDynamicSharedMemorySize, SMEM_SCORES);
    cudaFuncSetAttribute(attn_ctx_kernel,    cudaFuncAttributeMaxDynamicSharedMemorySize, SMEM_CTX);
    cudaFuncSetAttribute(mma_gemm<0>, cudaFuncAttributeMaxDynamicSharedMemorySize, SMEM_MMA);
    cudaFuncSetAttribute(mma_gemm<1>, cudaFuncAttributeMaxDynamicSharedMemorySize, SMEM_MMA);
    cudaFuncSetAttribute(mma_gemm<2>, cudaFuncAttributeMaxDynamicSharedMemorySize, SMEM_MMA);
    cudaFuncSetAttribute(mma_gemm<3>, cudaFuncAttributeMaxDynamicSharedMemorySize, SMEM_MMA);

    // setup: hidden copy + graph structure
    cudaMemcpyAsync(h, hidden, sizeof(float) * M_ * D_, cudaMemcpyDeviceToDevice);
    deg_kernel<<<B_, L_>>>(edges, dinv);
    cudaMemsetAsync(adj, 0, sizeof(float) * B_ * L_ * L_);
    adj_edge_kernel<<<(B_ * E_) / 256, 256>>>(edges, dinv, adj);
    adj_diag_kernel<<<(B_ * L_) / 256, 256>>>(dinv, adj);

    // transpose + split all weights [K,N] -> hi/lo [N,K]
    dim3 tb(32, 8);
    transpose_split<<<dim3(TD_/32, D_/32, NL_), tb>>>(Wqkv, wTh + OFF_QKV, wTl + OFF_QKV, D_, TD_);
    transpose_split<<<dim3(D_/32,  D_/32, NL_), tb>>>(Wo,   wTh + OFF_WO,  wTl + OFF_WO,  D_, D_);
    transpose_split<<<dim3(D_/32,  D_/32, NL_), tb>>>(m1_W, wTh + OFF_M1,  wTl + OFF_M1,  D_, D_);
    transpose_split<<<dim3(D_/32,  D_/32, NL_), tb>>>(c1_W, wTh + OFF_C1,  wTl + OFF_C1,  D_, D_);
    transpose_split<<<dim3(D_/32,  D_/32, NL_), tb>>>(c2_W, wTh + OFF_C2,  wTl + OFF_C2,  D_, D_);
    transpose_split<<<dim3(D_/32,  D_/32, NL_), tb>>>(m2_W, wTh + OFF_M2,  wTl + OFF_M2,  D_, D_);
    transpose_split<<<dim3(D_/32,  D_/32, NL_), tb>>>(m3_W, wTh + OFF_M3,  wTl + OFF_M3,  D_, D_);
    transpose_split<<<dim3(DF_/32, D_/32, NL_), tb>>>(int_W, wTh + OFF_INT, wTl + OFF_INT, D_, DF_);
    transpose_split<<<dim3(D_/32,  DF_/32, NL_), tb>>>(out_W, wTh + OFF_OUT, wTl + OFF_OUT, DF_, D_);

    const long sAdj = (long)L_ * L_;
    const long sBat = (long)L_ * D_;
    const long sYt  = (long)D_ * L_;

    for (int l = 0; l < NL_; l++) {
        const long oQ = OFF_QKV + (long)l * TD_ * D_;
        const long oW = OFF_WO  + (long)l * D_ * D_;
        const long o1 = OFF_M1  + (long)l * D_ * D_;
        const long oc1 = OFF_C1 + (long)l * D_ * D_;
        const long oc2 = OFF_C2 + (long)l * D_ * D_;
        const long o2 = OFF_M2  + (long)l * D_ * D_;
        const long o3 = OFF_M3  + (long)l * D_ * D_;
        const long oi = OFF_INT + (long)l * DF_ * D_;
        const long oo = OFF_OUT + (long)l * D_ * DF_;

        const float* bqkv_l = bqkv + (long)l * TD_;
        const float* bo_l   = bo   + (long)l * D_;
        const float* ln1s = ln1_s + (long)l * D_;
        const float* ln1b = ln1_b + (long)l * D_;
        const float* n1s  = n1_s + (long)l * D_;
        const float* n1b  = n1_b + (long)l * D_;
        const float* m1b  = m1_b + (long)l * D_;
        const float* c1b  = c1_b + (long)l * D_;
        const float* c2b  = c2_b + (long)l * D_;
        const float* n2s  = n2_s + (long)l * D_;
        const float* n2b  = n2_b + (long)l * D_;
        const float* m2b  = m2_b + (long)l * D_;
        const float* m3b  = m3_b + (long)l * D_;
        const float* intb = int_b + (long)l * DF_;
        const float* outb = out_b + (long)l * D_;
        const float* ln2s = ln2_s + (long)l * D_;
        const float* ln2b = ln2_b + (long)l * D_;

        // qkv = h @ Wqkv + b
        launch_mma(0, h, wTh + oQ, wTl + oQ, bqkv_l, 0, qkv, M_, TD_, D_, 1, 0, 0, 0);
        // attention
        attn_scores_kernel<<<dim3(B_ * H_, L_ / 64), 256, SMEM_SCORES>>>(qkv, P);
        attn_ctx_kernel<<<dim3(B_ * H_, L_ / 64), 256, SMEM_CTX>>>(qkv, P, ctx);
        // h1 = LN(ctx @ Wo + bo + h)
        launch_mma(1, ctx, wTh + oW, wTl + oW, bo_l, h, y, M_, D_, D_, 1, 0, 0, 0);
        ln_kernel<<<M_, 256>>>(y, ln1s, ln1b, h1);
        // res = gelu(h1 @ m3 + b)
        launch_mma(2, h1, wTh + o3, wTl + o3, m3b, 0, res, M_, D_, D_, 1, 0, 0, 0);
        // x = gelu(LN(h1,n1) @ m1 + b)
        ln_kernel<<<M_, 256>>>(h1, n1s, n1b, y);
        launch_mma(2, y, wTh + o1, wTl + o1, m1b, 0, x, M_, D_, D_, 1, 0, 0, 0);
        // GCN 1: y = x @ c1W ; x = gelu(Adj @ y + c1b)
        launch_mma(0, x, wTh + oc1, wTl + oc1, 0, 0, y, M_, D_, D_, 1, 0, 0, 0);
        transpose_split<<<dim3(D_/32, L_/32, B_), tb>>>(y, yth, ytl, L_, D_);
        launch_mma(2, adj, yth, ytl, c1b, 0, x, L_, D_, L_, B_, sAdj, sYt, sBat);
        // GCN 2
        launch_mma(0, x, wTh + oc2, wTl + oc2, 0, 0, y, M_, D_, D_, 1, 0, 0, 0);
        transpose_split<<<dim3(D_/32, L_/32, B_), tb>>>(y, yth, ytl, L_, D_);
        launch_mma(2, adj, yth, ytl, c2b, 0, x, L_, D_, L_, B_, sAdj, sYt, sBat);
        // g = res + gelu(LN(x,n2) @ m2 + b)
        ln_kernel<<<M_, 256>>>(x, n2s, n2b, y);
        launch_mma(3, y, wTh + o2, wTl + o2, m2b, res, gg, M_, D_, D_, 1, 0, 0, 0);
        // FFN
        launch_mma(2, gg, wTh + oi, wTl + oi, intb, 0, mid, M_, DF_, D_, 1, 0, 0, 0);
        launch_mma(1, mid, wTh + oo, wTl + oo, outb, gg, y, M_, D_, DF_, 1, 0, 0, 0);
        ln_kernel<<<M_, 256>>>(y, ln2s, ln2b, (l == NL_ - 1) ? (float*)d_out : h);
    }
}

// round 6
// speedup vs baseline: 1.7288x; 1.4068x over previous
#include <cuda_runtime.h>
#include <cuda_bf16.h>
#include <math.h>
#include <stdint.h>

// ---------------- problem constants ----------------
#define B_   8
#define L_   512
#define D_   768
#define NL_  12
#define E_   8192
#define H_   12
#define DH_  64
#define DF_  3072
#define M_   4096       // B_*L_
#define TD_  2304       // 3*D_

// ---------------- mma-gemm tile config ----------------
#define TM_T 128
#define TN_T 256
#define TK_T 32
#define AST  36                       // A row stride (floats)
#define BST  40                       // B row stride (bf16) - conflict-free
#define A_FLOATS (TM_T * AST)         // 4608 floats per stage
#define B_ELEMS  (TN_T * BST)         // 10240 bf16 per stage per array
#define SMEM_MMA (2 * A_FLOATS * 4 + 4 * B_ELEMS * 2)   // 118784 bytes

// ---------------- scratch (static device memory) ----------------
__device__ float g_h  [M_ * D_];
__device__ float g_qkv[M_ * TD_];
__device__ float g_P  [B_ * H_ * L_ * L_];
__device__ float g_ctx[M_ * D_];
__device__ float g_h1 [M_ * D_];
__device__ float g_res[M_ * D_];
__device__ float g_x  [M_ * D_];
__device__ float g_y  [M_ * D_];
__device__ float g_g  [M_ * D_];
__device__ float g_mid[M_ * DF_];
__device__ float g_adj[B_ * L_ * L_];
__device__ float g_dinv[B_ * L_];
__device__ __nv_bfloat16 g_yth[B_ * D_ * L_];   // transposed activations hi
__device__ __nv_bfloat16 g_ytl[B_ * D_ * L_];   // transposed activations lo
__device__ __nv_bfloat16 g_wTh[120324096];      // transposed weights hi
__device__ __nv_bfloat16 g_wTl[120324096];      // transposed weights lo

// transposed-weight offsets (elements)
#define OFF_QKV 0L
#define OFF_WO  21233664L
#define OFF_M1  28311552L
#define OFF_C1  35389440L
#define OFF_C2  42467328L
#define OFF_M2  49545216L
#define OFF_M3  56623104L
#define OFF_INT 63700992L
#define OFF_OUT 92012544L

// ---------------- helpers ----------------
__device__ __forceinline__ uint32_t smem_u32(const void* p) {
    uint32_t a;
    asm("{ .reg .u64 t; cvta.to.shared.u64 t, %1; cvt.u32.u64 %0, t; }" : "=r"(a) : "l"(p));
    return a;
}
__device__ __forceinline__ float gelu_f(float v) {
    return 0.5f * v * (1.0f + erff(v * 0.7071067811865475f));
}
__device__ __forceinline__ void cp16(uint32_t dst, const void* src) {
    asm volatile("cp.async.cg.shared.global [%0], [%1], 16;" :: "r"(dst), "l"(src));
}
#define CP_COMMIT() asm volatile("cp.async.commit_group;" ::: "memory")
#define CP_WAIT(n)  asm volatile("cp.async.wait_group %0;" :: "n"(n) : "memory")

// split a float2 into packed bf16x2 hi and lo
__device__ __forceinline__ void split2(float2 v, uint32_t& hi, uint32_t& lo) {
    __nv_bfloat162 h = __floats2bfloat162_rn(v.x, v.y);
    float rx = v.x - __bfloat162float(h.x);
    float ry = v.y - __bfloat162float(h.y);
    __nv_bfloat162 l = __floats2bfloat162_rn(rx, ry);
    hi = *reinterpret_cast<uint32_t*>(&h);
    lo = *reinterpret_cast<uint32_t*>(&l);
}

__device__ __forceinline__ void mma_bf16(float c[4], const uint32_t a[4], const uint32_t b[2]) {
    asm volatile(
        "mma.sync.aligned.m16n8k16.row.col.f32.bf16.bf16.f32 "
        "{%0,%1,%2,%3}, {%4,%5,%6,%7}, {%8,%9}, {%0,%1,%2,%3};"
        : "+f"(c[0]), "+f"(c[1]), "+f"(c[2]), "+f"(c[3])
        : "r"(a[0]), "r"(a[1]), "r"(a[2]), "r"(a[3]), "r"(b[0]), "r"(b[1]));
}

// ---------------- bf16x3 mma.sync GEMM ----------------
// C[M,N] = epi( A[M,K] @ (Bh+Bl)[N,K]^T + bias , add )
// EPI: 0=bias, 1=bias+add, 2=gelu(bias+acc), 3=gelu(bias+acc)+add
template <int EPI>
__global__ __launch_bounds__(256, 1)
void mma_gemm(const float* __restrict__ A,
              const __nv_bfloat16* __restrict__ Bh, const __nv_bfloat16* __restrict__ Bl,
              const float* __restrict__ bias, const float* __restrict__ add,
              float* __restrict__ C, int K, int N, long sA, long sB, long sC)
{
    extern __shared__ float sm[];
    float* Asm = sm;                                              // [2][128][36] fp32
    __nv_bfloat16* Bhsm = (__nv_bfloat16*)(sm + 2 * A_FLOATS);    // [2][256][40] bf16
    __nv_bfloat16* Blsm = Bhsm + 2 * B_ELEMS;                     // [2][256][40] bf16
    const uint32_t sA_u  = smem_u32(Asm);
    const uint32_t sBh_u = smem_u32(Bhsm);
    const uint32_t sBl_u = smem_u32(Blsm);

    const int tid = threadIdx.x;
    const long z = blockIdx.z;
    A  += z * sA;
    Bh += z * sB;
    Bl += z * sB;
    C  += z * sC;
    const float* addp = (EPI == 1 || EPI == 3) ? add + z * sC : (const float*)0;

    const int m0 = blockIdx.y * TM_T;
    const int n0 = blockIdx.x * TN_T;
    const int wid = tid >> 5, lane = tid & 31;
    const int wm = wid >> 2, wn = wid & 3;       // 2 x 4 warps
    const int gid = lane >> 2, tq = lane & 3;

    float c[4][8][4];
    #pragma unroll
    for (int mt = 0; mt < 4; mt++)
        #pragma unroll
        for (int nt = 0; nt < 8; nt++)
            #pragma unroll
            for (int i = 0; i < 4; i++) c[mt][nt][i] = 0.f;

    const int nck = K / TK_T;

    auto prefetch = [&](int s, int k0) {
        // A: 128 rows x 32 floats = 1024 cp16
        #pragma unroll
        for (int i = 0; i < 4; i++) {
            int t = tid + i * 256;
            int r = t >> 3, cc = t & 7;
            cp16(sA_u + (s * A_FLOATS + r * AST + cc * 4) * 4,
                 A + (long)(m0 + r) * K + k0 + cc * 4);
        }
        // B hi/lo: 256 rows x 32 bf16 = 1024 cp16 each
        #pragma unroll
        for (int i = 0; i < 4; i++) {
            int t = tid + i * 256;
            int r = t >> 2, cc = t & 3;
            cp16(sBh_u + (s * B_ELEMS + r * BST + cc * 8) * 2,
                 Bh + (long)(n0 + r) * K + k0 + cc * 8);
        }
        #pragma unroll
        for (int i = 0; i < 4; i++) {
            int t = tid + i * 256;
            int r = t >> 2, cc = t & 3;
            cp16(sBl_u + (s * B_ELEMS + r * BST + cc * 8) * 2,
                 Bl + (long)(n0 + r) * K + k0 + cc * 8);
        }
        CP_COMMIT();
    };

    prefetch(0, 0);

    for (int ck = 0; ck < nck; ck++) {
        if (ck + 1 < nck) {
            prefetch((ck + 1) & 1, (ck + 1) * TK_T);
            CP_WAIT(1);
        } else {
            CP_WAIT(0);
        }
        __syncthreads();

        const float* Ab = Asm + (ck & 1) * A_FLOATS + (wm * 64) * AST;
        const __nv_bfloat16* Bhb = Bhsm + (ck & 1) * B_ELEMS + (wn * 64) * BST;
        const __nv_bfloat16* Blb = Blsm + (ck & 1) * B_ELEMS + (wn * 64) * BST;

        #pragma unroll
        for (int kk = 0; kk < 2; kk++) {
            const int kb = kk * 16 + 2 * tq;
            uint32_t ah[4][4], al[4][4];
            #pragma unroll
            for (int mt = 0; mt < 4; mt++) {
                const int r0a = (mt * 16 + gid) * AST;
                const int r1a = (mt * 16 + gid + 8) * AST;
                float2 v0 = *(const float2*)&Ab[r0a + kb];
                float2 v1 = *(const float2*)&Ab[r1a + kb];
                float2 v2 = *(const float2*)&Ab[r0a + kb + 8];
                float2 v3 = *(const float2*)&Ab[r1a + kb + 8];
                split2(v0, ah[mt][0], al[mt][0]);
                split2(v1, ah[mt][1], al[mt][1]);
                split2(v2, ah[mt][2], al[mt][2]);
                split2(v3, ah[mt][3], al[mt][3]);
            }
            uint32_t bhf[8][2], blf[8][2];
            #pragma unroll
            for (int nt = 0; nt < 8; nt++) {
                const int base = (nt * 8 + gid) * BST + kb;
                bhf[nt][0] = *(const uint32_t*)&Bhb[base];
                bhf[nt][1] = *(const uint32_t*)&Bhb[base + 8];
                blf[nt][0] = *(const uint32_t*)&Blb[base];
                blf[nt][1] = *(const uint32_t*)&Blb[base + 8];
            }
            #pragma unroll
            for (int mt = 0; mt < 4; mt++)
                #pragma unroll
                for (int nt = 0; nt < 8; nt++) {
                    mma_bf16(c[mt][nt], al[mt], bhf[nt]);
                    mma_bf16(c[mt][nt], ah[mt], blf[nt]);
                    mma_bf16(c[mt][nt], ah[mt], bhf[nt]);
                }
        }
        __syncthreads();
    }

    // ---- epilogue ----
    #pragma unroll
    for (int mt = 0; mt < 4; mt++) {
        const int r0 = m0 + wm * 64 + mt * 16 + gid;
        #pragma unroll
        for (int nt = 0; nt < 8; nt++) {
            const int col = n0 + wn * 64 + nt * 8 + tq * 2;
            float bx = 0.f, by = 0.f;
            if (bias) { bx = bias[col]; by = bias[col + 1]; }
            #pragma unroll
            for (int half = 0; half < 2; half++) {
                const int r = r0 + half * 8;
                float vx = c[mt][nt][half * 2 + 0] + bx;
                float vy = c[mt][nt][half * 2 + 1] + by;
                if (EPI == 2 || EPI == 3) { vx = gelu_f(vx); vy = gelu_f(vy); }
                if (EPI == 1 || EPI == 3) {
                    const float* ap = &addp[(long)r * N + col];
                    vx += ap[0]; vy += ap[1];
                }
                float2 v = make_float2(vx, vy);
                *(float2*)&C[(long)r * N + col] = v;
            }
        }
    }
}

// ---------------- split transpose: in[Z][R][C] fp32 -> hi/lo bf16 out[Z][C][R] ----------------
__global__ void transpose_split(const float* __restrict__ in,
                                __nv_bfloat16* __restrict__ outh,
                                __nv_bfloat16* __restrict__ outl,
                                int R, int C)
{
    __shared__ float t[32][33];
    const long z = blockIdx.z;
    in   += z * (long)R * C;
    outh += z * (long)R * C;
    outl += z * (long)R * C;
    const int c0 = blockIdx.x * 32, r0 = blockIdx.y * 32;
    const int tx = threadIdx.x, ty = threadIdx.y;
    #pragma unroll
    for (int i = 0; i < 32; i += 8)
        t[ty + i][tx] = in[(long)(r0 + ty + i) * C + c0 + tx];
    __syncthreads();
    #pragma unroll
    for (int i = 0; i < 32; i += 8) {
        float v = t[tx][ty + i];
        __nv_bfloat16 hb = __float2bfloat16_rn(v);
        float lo = v - __bfloat162float(hb);
        const long o = (long)(c0 + ty + i) * R + r0 + tx;
        outh[o] = hb;
        outl[o] = __float2bfloat16_rn(lo);
    }
}

// ---------------- LayerNorm ----------------
__global__ void ln_kernel(const float* __restrict__ in,
                          const float* __restrict__ gam,
                          const float* __restrict__ bet,
                          float* __restrict__ out)
{
    __shared__ float red[8];
    const int row = blockIdx.x;
    const int t = threadIdx.x;
    const int lane = t & 31, w = t >> 5;
    const float* xp = in + (long)row * D_;

    float v0 = xp[t], v1 = xp[t + 256], v2 = xp[t + 512];
    float s = v0 + v1 + v2;
    #pragma unroll
    for (int o = 16; o > 0; o >>= 1) s += __shfl_xor_sync(0xffffffffu, s, o);
    if (lane == 0) red[w] = s;
    __syncthreads();
    s = 0.f;
    #pragma unroll
    for (int i = 0; i < 8; i++) s += red[i];
    const float mean = s * (1.f / 768.f);
    __syncthreads();

    float d0 = v0 - mean, d1 = v1 - mean, d2 = v2 - mean;
    float q = d0 * d0 + d1 * d1 + d2 * d2;
    #pragma unroll
    for (int o = 16; o > 0; o >>= 1) q += __shfl_xor_sync(0xffffffffu, q, o);
    if (lane == 0) red[w] = q;
    __syncthreads();
    q = 0.f;
    #pragma unroll
    for (int i = 0; i < 8; i++) q += red[i];
    const float r = rsqrtf(q * (1.f / 768.f) + 1e-12f);

    float* op = out + (long)row * D_;
    op[t]       = d0 * r * gam[t]       + bet[t];
    op[t + 256] = d1 * r * gam[t + 256] + bet[t + 256];
    op[t + 512] = d2 * r * gam[t + 512] + bet[t + 512];
}

// ---------------- attention: scores + softmax -> P ----------------
__global__ void attn_scores_kernel(const float* __restrict__ qkv, float* __restrict__ P)
{
    extern __shared__ float smf[];
    float* Ks = smf;
    float* qs = smf + 512 * 65;
    const int bh = blockIdx.x;
    const int b = bh / H_, head = bh % H_;
    const int q0 = blockIdx.y * 64;
    const int tid = threadIdx.x;
    const float* base = qkv + (long)b * L_ * TD_;

    for (int id = tid; id < 512 * 16; id += 256) {
        int k = id >> 4, c = (id & 15) << 2;
        float4 v = *(const float4*)&base[(long)k * TD_ + D_ + head * DH_ + c];
        float* p = &Ks[k * 65 + c];
        p[0] = v.x; p[1] = v.y; p[2] = v.z; p[3] = v.w;
    }
    for (int id = tid; id < 64 * 16; id += 256) {
        int r = id >> 4, c = (id & 15) << 2;
        float4 v = *(const float4*)&base[(long)(q0 + r) * TD_ + head * DH_ + c];
        float* p = &qs[r * 65 + c];
        p[0] = v.x; p[1] = v.y; p[2] = v.z; p[3] = v.w;
    }
    __syncthreads();

    const int w = tid >> 5, lane = tid & 31;
    for (int rr = 0; rr < 8; rr++) {
        const int row = w * 8 + rr;
        float acc[16];
        #pragma unroll
        for (int j = 0; j < 16; j++) acc[j] = 0.f;
        const float* qp = &qs[row * 65];
        const float* kp = &Ks[lane * 65];
        #pragma unroll 4
        for (int d = 0; d < 64; d++) {
            float qd = qp[d];
            #pragma unroll
            for (int j = 0; j < 16; j++)
                acc[j] += qd * kp[j * (32 * 65) + d];
        }
        float mx = -3.0e38f;
        #pragma unroll
        for (int j = 0; j < 16; j++) { acc[j] *= 0.125f; mx = fmaxf(mx, acc[j]); }
        #pragma unroll
        for (int o = 16; o > 0; o >>= 1) mx = fmaxf(mx, __shfl_xor_sync(0xffffffffu, mx, o));
        float s = 0.f;
        #pragma unroll
        for (int j = 0; j < 16; j++) { acc[j] = __expf(acc[j] - mx); s += acc[j]; }
        #pragma unroll
        for (int o = 16; o > 0; o >>= 1) s += __shfl_xor_sync(0xffffffffu, s, o);
        const float inv = 1.f / s;
        float* Pp = P + ((long)bh * L_ + q0 + row) * L_;
        #pragma unroll
        for (int j = 0; j < 16; j++) Pp[lane + 32 * j] = acc[j] * inv;
    }
}

// ---------------- attention: ctx = P @ V ----------------
__global__ void attn_ctx_kernel(const float* __restrict__ qkv,
                                const float* __restrict__ P,
                                float* __restrict__ ctx)
{
    extern __shared__ float smf[];
    float* Vs = smf;
    float* Ps = smf + 512 * 65;
    const int bh = blockIdx.x;
    const int b = bh / H_, head = bh % H_;
    const int q0 = blockIdx.y * 64;
    const int tid = threadIdx.x;
    const float* base = qkv + (long)b * L_ * TD_;

    for (int id = tid; id < 512 * 16; id += 256) {
        int k = id >> 4, c = (id & 15) << 2;
        float4 v = *(const float4*)&base[(long)k * TD_ + 2 * D_ + head * DH_ + c];
        float* p = &Vs[k * 65 + c];
        p[0] = v.x; p[1] = v.y; p[2] = v.z; p[3] = v.w;
    }

    const int q = tid >> 2, dl = tid & 3;
    float acc[16];
    #pragma unroll
    for (int i = 0; i < 16; i++) acc[i] = 0.f;
    const float* Prow = P + ((long)bh * L_ + q0) * L_;

    for (int kt = 0; kt < 4; kt++) {
        __syncthreads();
        for (int id = tid; id < 64 * 32; id += 256) {
            int r = id >> 5, c = (id & 31) << 2;
            *(float4*)&Ps[r * 132 + c] =
                *(const float4*)&Prow[(long)r * L_ + kt * 128 + c];
        }
        __syncthreads();
        const float* pq = &Ps[q * 132];
        #pragma unroll 2
        for (int kk = 0; kk < 128; kk++) {
            float p = pq[kk];
            const float* vp = &Vs[(kt * 128 + kk) * 65 + dl];
            #pragma unroll
            for (int i = 0; i < 16; i++) acc[i] += p * vp[4 * i];
        }
    }
    float* cp = ctx + (long)(b * L_ + q0 + q) * D_ + head * DH_ + dl;
    #pragma unroll
    for (int i = 0; i < 16; i++) cp[4 * i] = acc[i];
}

// ---------------- GCN graph structure ----------------
__global__ void deg_kernel(const int* __restrict__ edges, float* __restrict__ dinv)
{
    __shared__ float sdeg[L_];
    const int b = blockIdx.x, t = threadIdx.x;
    sdeg[t] = 1.f;
    __syncthreads();
    const int* dst = edges + (long)b * 2 * E_ + E_;
    for (int e = t; e < E_; e += L_) atomicAdd(&sdeg[dst[e]], 1.f);
    __syncthreads();
    dinv[b * L_ + t] = rsqrtf(sdeg[t]);
}

__global__ void adj_edge_kernel(const int* __restrict__ edges,
                                const float* __restrict__ dinv,
                                float* __restrict__ adj)
{
    const int i = blockIdx.x * 256 + threadIdx.x;
    const int b = i / E_, e = i % E_;
    const int s = edges[(long)b * 2 * E_ + e];
    const int d = edges[(long)b * 2 * E_ + E_ + e];
    atomicAdd(&adj[((long)b * L_ + d) * L_ + s], dinv[b * L_ + s] * dinv[b * L_ + d]);
}

__global__ void adj_diag_kernel(const float* __restrict__ dinv, float* __restrict__ adj)
{
    const int i = blockIdx.x * 256 + threadIdx.x;
    const int b = i / L_, n = i % L_;
    const float di = dinv[i];
    adj[((long)b * L_ + n) * L_ + n] += di * di;
}

// ---------------- host side ----------------
static void launch_mma(int epi, const float* A,
                       const __nv_bfloat16* Bh, const __nv_bfloat16* Bl,
                       const float* bias, const float* add, float* C,
                       int Mr, int N, int K, int batch,
                       long sA, long sB, long sC)
{
    dim3 grid(N / TN_T, Mr / TM_T, batch), block(256);
    switch (epi) {
        case 0: mma_gemm<0><<<grid, block, SMEM_MMA>>>(A, Bh, Bl, bias, add, C, K, N, sA, sB, sC); break;
        case 1: mma_gemm<1><<<grid, block, SMEM_MMA>>>(A, Bh, Bl, bias, add, C, K, N, sA, sB, sC); break;
        case 2: mma_gemm<2><<<grid, block, SMEM_MMA>>>(A, Bh, Bl, bias, add, C, K, N, sA, sB, sC); break;
        case 3: mma_gemm<3><<<grid, block, SMEM_MMA>>>(A, Bh, Bl, bias, add, C, K, N, sA, sB, sC); break;
    }
}

extern "C" void kernel_launch(void* const* d_in, const int* in_sizes, int n_in,
                              void* d_out, int out_size)
{
    const float* hidden = (const float*)d_in[0];
    const int*   edges  = (const int*)  d_in[1];
    const float* Wqkv   = (const float*)d_in[2];
    const float* bqkv   = (const float*)d_in[3];
    const float* Wo     = (const float*)d_in[4];
    const float* bo     = (const float*)d_in[5];
    const float* ln1_s  = (const float*)d_in[6];
    const float* ln1_b  = (const float*)d_in[7];
    const float* n1_s   = (const float*)d_in[8];
    const float* n1_b   = (const float*)d_in[9];
    const float* m1_W   = (const float*)d_in[10];
    const float* m1_b   = (const float*)d_in[11];
    const float* c1_W   = (const float*)d_in[12];
    const float* c1_b   = (const float*)d_in[13];
    const float* c2_W   = (const float*)d_in[14];
    const float* c2_b   = (const float*)d_in[15];
    const float* n2_s   = (const float*)d_in[16];
    const float* n2_b   = (const float*)d_in[17];
    const float* m2_W   = (const float*)d_in[18];
    const float* m2_b   = (const float*)d_in[19];
    const float* m3_W   = (const float*)d_in[20];
    const float* m3_b   = (const float*)d_in[21];
    const float* int_W  = (const float*)d_in[22];
    const float* int_b  = (const float*)d_in[23];
    const float* out_W  = (const float*)d_in[24];
    const float* out_b  = (const float*)d_in[25];
    const float* ln2_s  = (const float*)d_in[26];
    const float* ln2_b  = (const float*)d_in[27];

    float *h, *qkv, *P, *ctx, *h1, *res, *x, *y, *gg, *mid, *adj, *dinv;
    __nv_bfloat16 *yth, *ytl, *wTh, *wTl;
    cudaGetSymbolAddress((void**)&h,    g_h);
    cudaGetSymbolAddress((void**)&qkv,  g_qkv);
    cudaGetSymbolAddress((void**)&P,    g_P);
    cudaGetSymbolAddress((void**)&ctx,  g_ctx);
    cudaGetSymbolAddress((void**)&h1,   g_h1);
    cudaGetSymbolAddress((void**)&res,  g_res);
    cudaGetSymbolAddress((void**)&x,    g_x);
    cudaGetSymbolAddress((void**)&y,    g_y);
    cudaGetSymbolAddress((void**)&gg,   g_g);
    cudaGetSymbolAddress((void**)&mid,  g_mid);
    cudaGetSymbolAddress((void**)&adj,  g_adj);
    cudaGetSymbolAddress((void**)&dinv, g_dinv);
    cudaGetSymbolAddress((void**)&yth,  g_yth);
    cudaGetSymbolAddress((void**)&ytl,  g_ytl);
    cudaGetSymbolAddress((void**)&wTh,  g_wTh);
    cudaGetSymbolAddress((void**)&wTl,  g_wTl);

    const int SMEM_SCORES = (512 * 65 + 64 * 65) * 4;
    const int SMEM_CTX    = (512 * 65 + 64 * 132) * 4;
    cudaFuncSetAttribute(attn_scores_kernel, cudaFuncAttributeMaxDynamicSharedMemorySize, SMEM_SCORES);
    cudaFuncSetAttribute(attn_ctx_kernel,    cudaFuncAttributeMaxDynamicSharedMemorySize, SMEM_CTX);
    cudaFuncSetAttribute(mma_gemm<0>, cudaFuncAttributeMaxDynamicSharedMemorySize, SMEM_MMA);
    cudaFuncSetAttribute(mma_gemm<1>, cudaFuncAttributeMaxDynamicSharedMemorySize, SMEM_MMA);
    cudaFuncSetAttribute(mma_gemm<2>, cudaFuncAttributeMaxDynamicSharedMemorySize, SMEM_MMA);
    cudaFuncSetAttribute(mma_gemm<3>, cudaFuncAttributeMaxDynamicSharedMemorySize, SMEM_MMA);

    // setup: hidden copy + graph structure
    cudaMemcpyAsync(h, hidden, sizeof(float) * M_ * D_, cudaMemcpyDeviceToDevice);
    deg_kernel<<<B_, L_>>>(edges, dinv);
    cudaMemsetAsync(adj, 0, sizeof(float) * B_ * L_ * L_);
    adj_edge_kernel<<<(B_ * E_) / 256, 256>>>(edges, dinv, adj);
    adj_diag_kernel<<<(B_ * L_) / 256, 256>>>(dinv, adj);

    // transpose + bf16-split all weights [K,N] -> hi/lo [N,K]
    dim3 tb(32, 8);
    transpose_split<<<dim3(TD_/32, D_/32, NL_), tb>>>(Wqkv, wTh + OFF_QKV, wTl + OFF_QKV, D_, TD_);
    transpose_split<<<dim3(D_/32,  D_/32, NL_), tb>>>(Wo,   wTh + OFF_WO,  wTl + OFF_WO,  D_, D_);
    transpose_split<<<dim3(D_/32,  D_/32, NL_), tb>>>(m1_W, wTh + OFF_M1,  wTl + OFF_M1,  D_, D_);
    transpose_split<<<dim3(D_/32,  D_/32, NL_), tb>>>(c1_W, wTh + OFF_C1,  wTl + OFF_C1,  D_, D_);
    transpose_split<<<dim3(D_/32,  D_/32, NL_), tb>>>(c2_W, wTh + OFF_C2,  wTl + OFF_C2,  D_, D_);
    transpose_split<<<dim3(D_/32,  D_/32, NL_), tb>>>(m2_W, wTh + OFF_M2,  wTl + OFF_M2,  D_, D_);
    transpose_split<<<dim3(D_/32,  D_/32, NL_), tb>>>(m3_W, wTh + OFF_M3,  wTl + OFF_M3,  D_, D_);
    transpose_split<<<dim3(DF_/32, D_/32, NL_), tb>>>(int_W, wTh + OFF_INT, wTl + OFF_INT, D_, DF_);
    transpose_split<<<dim3(D_/32,  DF_/32, NL_), tb>>>(out_W, wTh + OFF_OUT, wTl + OFF_OUT, DF_, D_);

    const long sAdj = (long)L_ * L_;
    const long sBat = (long)L_ * D_;
    const long sYt  = (long)D_ * L_;

    for (int l = 0; l < NL_; l++) {
        const long oQ = OFF_QKV + (long)l * TD_ * D_;
        const long oW = OFF_WO  + (long)l * D_ * D_;
        const long o1 = OFF_M1  + (long)l * D_ * D_;
        const long oc1 = OFF_C1 + (long)l * D_ * D_;
        const long oc2 = OFF_C2 + (long)l * D_ * D_;
        const long o2 = OFF_M2  + (long)l * D_ * D_;
        const long o3 = OFF_M3  + (long)l * D_ * D_;
        const long oi = OFF_INT + (long)l * DF_ * D_;
        const long oo = OFF_OUT + (long)l * D_ * DF_;

        const float* bqkv_l = bqkv + (long)l * TD_;
        const float* bo_l   = bo   + (long)l * D_;
        const float* ln1s = ln1_s + (long)l * D_;
        const float* ln1b = ln1_b + (long)l * D_;
        const float* n1s  = n1_s + (long)l * D_;
        const float* n1b  = n1_b + (long)l * D_;
        const float* m1b  = m1_b + (long)l * D_;
        const float* c1b  = c1_b + (long)l * D_;
        const float* c2b  = c2_b + (long)l * D_;
        const float* n2s  = n2_s + (long)l * D_;
        const float* n2b  = n2_b + (long)l * D_;
        const float* m2b  = m2_b + (long)l * D_;
        const float* m3b  = m3_b + (long)l * D_;
        const float* intb = int_b + (long)l * DF_;
        const float* outb = out_b + (long)l * D_;
        const float* ln2s = ln2_s + (long)l * D_;
        const float* ln2b = ln2_b + (long)l * D_;

        // qkv = h @ Wqkv + b
        launch_mma(0, h, wTh + oQ, wTl + oQ, bqkv_l, 0, qkv, M_, TD_, D_, 1, 0, 0, 0);
        // attention
        attn_scores_kernel<<<dim3(B_ * H_, L_ / 64), 256, SMEM_SCORES>>>(qkv, P);
        attn_ctx_kernel<<<dim3(B_ * H_, L_ / 64), 256, SMEM_CTX>>>(qkv, P, ctx);
        // h1 = LN(ctx @ Wo + bo + h)
        launch_mma(1, ctx, wTh + oW, wTl + oW, bo_l, h, y, M_, D_, D_, 1, 0, 0, 0);
        ln_kernel<<<M_, 256>>>(y, ln1s, ln1b, h1);
        // res = gelu(h1 @ m3 + b)
        launch_mma(2, h1, wTh + o3, wTl + o3, m3b, 0, res, M_, D_, D_, 1, 0, 0, 0);
        // x = gelu(LN(h1,n1) @ m1 + b)
        ln_kernel<<<M_, 256>>>(h1, n1s, n1b, y);
        launch_mma(2, y, wTh + o1, wTl + o1, m1b, 0, x, M_, D_, D_, 1, 0, 0, 0);
        // GCN 1: y = x @ c1W ; x = gelu(Adj @ y + c1b)
        launch_mma(0, x, wTh + oc1, wTl + oc1, 0, 0, y, M_, D_, D_, 1, 0, 0, 0);
        transpose_split<<<dim3(D_/32, L_/32, B_), tb>>>(y, yth, ytl, L_, D_);
        launch_mma(2, adj, yth, ytl, c1b, 0, x, L_, D_, L_, B_, sAdj, sYt, sBat);
        // GCN 2
        launch_mma(0, x, wTh + oc2, wTl + oc2, 0, 0, y, M_, D_, D_, 1, 0, 0, 0);
        transpose_split<<<dim3(D_/32, L_/32, B_), tb>>>(y, yth, ytl, L_, D_);
        launch_mma(2, adj, yth, ytl, c2b, 0, x, L_, D_, L_, B_, sAdj, sYt, sBat);
        // g = res + gelu(LN(x,n2) @ m2 + b)
        ln_kernel<<<M_, 256>>>(x, n2s, n2b, y);
        launch_mma(3, y, wTh + o2, wTl + o2, m2b, res, gg, M_, D_, D_, 1, 0, 0, 0);
        // FFN
        launch_mma(2, gg, wTh + oi, wTl + oi, intb, 0, mid, M_, DF_, D_, 1, 0, 0, 0);
        launch_mma(1, mid, wTh + oo, wTl + oo, outb, gg, y, M_, D_, DF_, 1, 0, 0, 0);
        ln_kernel<<<M_, 256>>>(y, ln2s, ln2b, (l == NL_ - 1) ? (float*)d_out : h);
    }
}